// round 4
// baseline (speedup 1.0000x reference)
#include <cuda_runtime.h>

// Scratch: pooled means [8 batches x 128 channels]
__device__ float g_pooled[1024];

// Hierarchical completion counters: 32 partition counters on distinct 128B
// L2 lines (32 blocks each), plus one final counter. Avoids the ~28-cyc/op
// serialization of 1024 atomics on a single address.
struct __align__(128) PadCnt { unsigned int v; unsigned int pad[31]; };
__device__ PadCnt g_cnt_part[32];
__device__ unsigned int g_cnt_final = 0;

// Fused kernel:
//  Phase A (all 1024 blocks): pooled[b,c] = (1/65536) * sum_{h even, w even} b[b,c,h,w]
//  Phase B (last-arriving block only): hidden = relu(pooled @ fc1_w^T); out = hidden @ fc2_w^T
__global__ __launch_bounds__(256, 8) void fused_kernel(const float* __restrict__ bsrc,
                                                       const float* __restrict__ fc1_w,
                                                       const float* __restrict__ fc2_w,
                                                       float* __restrict__ out) {
    const int blk = blockIdx.x;                    // 0..1023 = b*128 + c
    const int tid = threadIdx.x;

    // ---------- Phase A: strided pooled sum over even rows ----------
    const float4* __restrict__ base =
        reinterpret_cast<const float4*>(bsrc) + (size_t)blk * (65536 / 4);

    float sum = 0.0f;
    // 128 even rows x 64 float4 per row = 8192 float4 per block; 32 per thread.
    #pragma unroll 8
    for (int i = tid; i < 128 * 64; i += 256) {
        const int r  = i >> 6;        // even-row index 0..127  (h = 2*r)
        const int c4 = i & 63;        // float4 index within row
        float4 v = __ldg(&base[(size_t)(2 * r) * 64 + c4]);
        sum += v.x + v.z;
    }

    #pragma unroll
    for (int off = 16; off > 0; off >>= 1)
        sum += __shfl_xor_sync(0xFFFFFFFFu, sum, off);

    __shared__ float warp_sums[8];
    __shared__ int is_last;
    if ((tid & 31) == 0) warp_sums[tid >> 5] = sum;
    if (tid == 0) is_last = 0;
    __syncthreads();

    if (tid == 0) {
        float s = warp_sums[0];
        #pragma unroll
        for (int w = 1; w < 8; ++w) s += warp_sums[w];
        g_pooled[blk] = s * (1.0f / 65536.0f);
        __threadfence();                              // publish before counting

        // Two-level completion detection: 32 blocks per partition counter.
        unsigned int old = atomicAdd(&g_cnt_part[blk & 31].v, 1u);
        if (old == 31u) {
            unsigned int old2 = atomicAdd(&g_cnt_final, 1u);
            if (old2 == 31u) {
                // We are globally last. Reset counters for the next graph replay.
                g_cnt_final = 0u;
                #pragma unroll
                for (int p = 0; p < 32; ++p) g_cnt_part[p].v = 0u;
                is_last = 1;
            }
        }
    }
    __syncthreads();
    if (!is_last) return;

    // ---------- Phase B: tiny MLP (only the globally-last block runs this) ----------
    __shared__ __align__(16) float sp[1024];          // pooled [8][128]
    __shared__ __align__(16) float sh[256];           // hidden [8][32]

    #pragma unroll
    for (int k = 0; k < 4; ++k) {
        const int i = tid + k * 256;
        sp[i] = __ldcg(&g_pooled[i]);                 // L2-hot, bypass L1
    }
    __syncthreads();

    // hidden[b][j] = relu( sum_c pooled[b][c] * fc1_w[j][c] )
    {
        const int j  = tid & 31;                      // hidden unit 0..31
        const int bb = tid >> 5;                      // batch 0..7
        const float4* __restrict__ w4 = reinterpret_cast<const float4*>(fc1_w) + j * 32;
        const float4* __restrict__ p4 = reinterpret_cast<const float4*>(sp) + bb * 32;
        float s = 0.0f;
        #pragma unroll
        for (int k = 0; k < 32; ++k) {
            float4 w = __ldg(&w4[k]);
            float4 p = p4[k];
            s = fmaf(w.x, p.x, s);
            s = fmaf(w.y, p.y, s);
            s = fmaf(w.z, p.z, s);
            s = fmaf(w.w, p.w, s);
        }
        sh[tid] = fmaxf(s, 0.0f);                     // sh[b*32+j]
    }
    __syncthreads();

    // out[b][c] = sum_j hidden[b][j] * fc2_w[c][j]   (4 outputs per thread)
    #pragma unroll
    for (int k = 0; k < 4; ++k) {
        const int idx = tid + k * 256;                // 0..1023 = b*128 + c
        const int bb  = idx >> 7;
        const int c   = idx & 127;
        const float4* __restrict__ w4 = reinterpret_cast<const float4*>(fc2_w) + c * 8;
        const float4* __restrict__ h4 = reinterpret_cast<const float4*>(sh) + bb * 8;
        float s = 0.0f;
        #pragma unroll
        for (int q = 0; q < 8; ++q) {
            float4 w = __ldg(&w4[q]);
            float4 h = h4[q];
            s = fmaf(w.x, h.x, s);
            s = fmaf(w.y, h.y, s);
            s = fmaf(w.z, h.z, s);
            s = fmaf(w.w, h.w, s);
        }
        out[idx] = s;
    }
}

extern "C" void kernel_launch(void* const* d_in, const int* in_sizes, int n_in,
                              void* d_out, int out_size) {
    // metadata order: a, b, attn_w, attn_b, fc1_w, fc2_w
    const float* bsrc  = (const float*)d_in[1];
    const float* fc1_w = (const float*)d_in[4];
    const float* fc2_w = (const float*)d_in[5];
    float* out = (float*)d_out;   // [8,128,1,1] = 1024 floats

    fused_kernel<<<1024, 256>>>(bsrc, fc1_w, fc2_w, out);
}

// round 5
// speedup vs baseline: 1.1221x; 1.1221x over previous
#include <cuda_runtime.h>
#include <cstdint>

// Scratch: pooled means [8 batches x 128 channels]
__device__ float g_pooled[1024];

// Hierarchical completion counters (distinct 128B lines)
struct __align__(128) PadCnt { unsigned int v; unsigned int pad[31]; };
__device__ PadCnt g_cnt_part[32];
__device__ unsigned int g_cnt_final = 0;

__device__ __forceinline__ float4 ldg_nc_256(const float4* p) {
    float4 v;
    asm volatile("ld.global.nc.L2::256B.v4.f32 {%0,%1,%2,%3}, [%4];"
                 : "=f"(v.x), "=f"(v.y), "=f"(v.z), "=f"(v.w)
                 : "l"(p));
    return v;
}

// 512 blocks x 256 threads. Block handles planes 2*blk and 2*blk+1.
// Phase A: pooled[plane] = (1/65536) * sum over even h, even w.
// Phase B (globally-last block): tiny MLP.
__global__ __launch_bounds__(256, 4) void fused_kernel(const float* __restrict__ bsrc,
                                                       const float* __restrict__ fc1_w,
                                                       const float* __restrict__ fc2_w,
                                                       float* __restrict__ out) {
    const int blk = blockIdx.x;                    // 0..511
    const int tid = threadIdx.x;

    // Base of this block's 2-plane region, in float4 units (plane = 16384 f4)
    const float4* __restrict__ base =
        reinterpret_cast<const float4*>(bsrc) + (size_t)blk * 32768;

    // Even-element index space per block: 2 planes * 128 even rows * 64 f4 = 16384.
    // j -> plane = j>>13, even-row r = (j>>6)&127, col4 = j&63
    // f4 address = plane*16384 + r*128 + c4   (2r * 64 = r*128)
    float acc0 = 0.f, acc1 = 0.f;                  // per-plane accumulators
    #pragma unroll
    for (int kk = 0; kk < 64; kk += 8) {
        float4 v[8];
        #pragma unroll
        for (int u = 0; u < 8; ++u) {
            const int j  = tid + (kk + u) * 256;
            const int pl = j >> 13;
            const int r  = (j >> 6) & 127;
            const int c4 = j & 63;
            v[u] = ldg_nc_256(base + ((pl << 14) + (r << 7) + c4));
        }
        #pragma unroll
        for (int u = 0; u < 8; ++u) {
            const int j  = tid + (kk + u) * 256;
            const float s = v[u].x + v[u].z;
            if ((j >> 13) == 0) acc0 += s; else acc1 += s;
        }
    }

    // Reduce both plane sums across the block.
    #pragma unroll
    for (int off = 16; off > 0; off >>= 1) {
        acc0 += __shfl_xor_sync(0xFFFFFFFFu, acc0, off);
        acc1 += __shfl_xor_sync(0xFFFFFFFFu, acc1, off);
    }

    __shared__ float warp_sums[2][8];
    __shared__ int is_last;
    if ((tid & 31) == 0) {
        warp_sums[0][tid >> 5] = acc0;
        warp_sums[1][tid >> 5] = acc1;
    }
    if (tid == 0) is_last = 0;
    __syncthreads();

    if (tid == 0) {
        float s0 = warp_sums[0][0], s1 = warp_sums[1][0];
        #pragma unroll
        for (int w = 1; w < 8; ++w) { s0 += warp_sums[0][w]; s1 += warp_sums[1][w]; }
        g_pooled[2 * blk + 0] = s0 * (1.0f / 65536.0f);
        g_pooled[2 * blk + 1] = s1 * (1.0f / 65536.0f);
        __threadfence();

        unsigned int old = atomicAdd(&g_cnt_part[blk & 31].v, 1u);
        if (old == 15u) {                          // 512/32 = 16 blocks per partition
            unsigned int old2 = atomicAdd(&g_cnt_final, 1u);
            if (old2 == 31u) {
                g_cnt_final = 0u;
                #pragma unroll
                for (int p = 0; p < 32; ++p) g_cnt_part[p].v = 0u;
                is_last = 1;
            }
        }
    }
    __syncthreads();
    if (!is_last) return;

    // ---------- Phase B: tiny MLP ----------
    __shared__ __align__(16) float sp[1024];       // pooled [8][128]
    __shared__ __align__(16) float sh[256];        // hidden [8][32]

    #pragma unroll
    for (int k = 0; k < 4; ++k) {
        const int i = tid + k * 256;
        sp[i] = __ldcg(&g_pooled[i]);
    }
    __syncthreads();

    // hidden[b][j] = relu( sum_c pooled[b][c] * fc1_w[j][c] )
    {
        const int j  = tid & 31;
        const int bb = tid >> 5;
        const float4* __restrict__ w4 = reinterpret_cast<const float4*>(fc1_w) + j * 32;
        const float4* __restrict__ p4 = reinterpret_cast<const float4*>(sp) + bb * 32;
        float s = 0.0f;
        #pragma unroll
        for (int k = 0; k < 32; ++k) {
            float4 w = __ldg(&w4[k]);
            float4 p = p4[k];
            s = fmaf(w.x, p.x, s);
            s = fmaf(w.y, p.y, s);
            s = fmaf(w.z, p.z, s);
            s = fmaf(w.w, p.w, s);
        }
        sh[tid] = fmaxf(s, 0.0f);
    }
    __syncthreads();

    // out[b][c] = sum_j hidden[b][j] * fc2_w[c][j]
    #pragma unroll
    for (int k = 0; k < 4; ++k) {
        const int idx = tid + k * 256;             // b*128 + c
        const int bb  = idx >> 7;
        const int c   = idx & 127;
        const float4* __restrict__ w4 = reinterpret_cast<const float4*>(fc2_w) + c * 8;
        const float4* __restrict__ h4 = reinterpret_cast<const float4*>(sh) + bb * 8;
        float s = 0.0f;
        #pragma unroll
        for (int q = 0; q < 8; ++q) {
            float4 w = __ldg(&w4[q]);
            float4 h = h4[q];
            s = fmaf(w.x, h.x, s);
            s = fmaf(w.y, h.y, s);
            s = fmaf(w.z, h.z, s);
            s = fmaf(w.w, h.w, s);
        }
        out[idx] = s;
    }
}

extern "C" void kernel_launch(void* const* d_in, const int* in_sizes, int n_in,
                              void* d_out, int out_size) {
    // metadata order: a, b, attn_w, attn_b, fc1_w, fc2_w
    const float* bsrc  = (const float*)d_in[1];
    const float* fc1_w = (const float*)d_in[4];
    const float* fc2_w = (const float*)d_in[5];
    float* out = (float*)d_out;

    fused_kernel<<<512, 256>>>(bsrc, fc1_w, fc2_w, out);
}

// round 6
// speedup vs baseline: 1.1232x; 1.0010x over previous
#include <cuda_runtime.h>
#include <cstdint>

// Scratch: pooled means [8 batches x 128 channels]
__device__ float g_pooled[1024];

// Hierarchical completion counters (distinct 128B lines)
struct __align__(128) PadCnt { unsigned int v; unsigned int pad[31]; };
__device__ PadCnt g_cnt_part[32];
__device__ unsigned int g_cnt_final = 0;

#define STAGES          4
#define ROWS_PER_STAGE  8
#define STAGE_BYTES     (ROWS_PER_STAGE * 1024)   // 8 KB
#define TOTAL_STAGES    32                        // 2 planes * 16 stages

__device__ __forceinline__ uint32_t smem_u32(const void* p) {
    uint32_t a;
    asm("{ .reg .u64 t; cvta.to.shared.u64 t, %1; cvt.u32.u64 %0, t; }" : "=r"(a) : "l"(p));
    return a;
}

__device__ __forceinline__ void mbar_init(uint32_t mbar, uint32_t count) {
    asm volatile("mbarrier.init.shared.b64 [%0], %1;" :: "r"(mbar), "r"(count) : "memory");
}

__device__ __forceinline__ void wait_full(uint32_t mbar, uint32_t parity) {
    asm volatile(
        "{\n\t"
        ".reg .pred P;\n\t"
        "WL_%=:\n\t"
        "mbarrier.try_wait.parity.acquire.cta.shared::cta.b64 P, [%0], %1, 0x989680;\n\t"
        "@P bra WD_%=;\n\t"
        "bra WL_%=;\n\t"
        "WD_%=:\n\t"
        "}" :: "r"(mbar), "r"(parity) : "memory");
}

// Issue one stage: 8 bulk copies of one 1KB even-row each, completing on mbar.
__device__ __forceinline__ void issue_stage(uint32_t mbar, uint32_t dst,
                                            const char* __restrict__ base, int s) {
    asm volatile("mbarrier.arrive.expect_tx.shared.b64 _, [%0], %1;"
                 :: "r"(mbar), "r"((uint32_t)STAGE_BYTES) : "memory");
    // stage s: plane = s>>4, even-row group = s&15 (rows r = 8*(s&15)..+7, byte off r*2048)
    const char* src = base + ((size_t)(s >> 4) << 18) + ((size_t)(s & 15) * (ROWS_PER_STAGE * 2048));
    #pragma unroll
    for (int r = 0; r < ROWS_PER_STAGE; ++r) {
        asm volatile(
            "cp.async.bulk.shared::cta.global.mbarrier::complete_tx::bytes [%0], [%1], %2, [%3];"
            :: "r"(dst + r * 1024), "l"(src + (size_t)r * 2048),
               "r"(1024), "r"(mbar) : "memory");
    }
}

// 512 blocks x 256 threads, one wave. Block handles planes 2*blk, 2*blk+1 via a
// 4-stage cp.async.bulk pipeline; globally-last block runs the tiny MLP.
__global__ __launch_bounds__(256) void fused_kernel(const float* __restrict__ bsrc,
                                                    const float* __restrict__ fc1_w,
                                                    const float* __restrict__ fc2_w,
                                                    float* __restrict__ out) {
    __shared__ __align__(128) float stage_buf[STAGES][STAGE_BYTES / 4];
    __shared__ __align__(8)  unsigned long long mbar_store[STAGES];
    __shared__ float warp_sums[2][8];
    __shared__ int is_last;
    __shared__ __align__(16) float sp[1024];
    __shared__ __align__(16) float sh[256];

    const int blk = blockIdx.x;                 // 0..511
    const int tid = threadIdx.x;
    const char* __restrict__ base = (const char*)bsrc + ((size_t)blk << 19);  // 2 planes = 512 KB

    const uint32_t mb0 = smem_u32(&mbar_store[0]);
    const uint32_t sb0 = smem_u32(&stage_buf[0][0]);

    if (tid == 0) {
        is_last = 0;
        #pragma unroll
        for (int s = 0; s < STAGES; ++s) mbar_init(mb0 + 8 * s, 1);
    }
    __syncthreads();
    asm volatile("fence.proxy.async.shared::cta;" ::: "memory");

    // Prime the pipeline
    if (tid == 0) {
        #pragma unroll
        for (int s = 0; s < STAGES; ++s)
            issue_stage(mb0 + 8 * s, sb0 + s * STAGE_BYTES, base, s);
    }

    float acc0 = 0.0f, acc1 = 0.0f;
    for (int i = 0; i < TOTAL_STAGES; ++i) {
        const int slot = i & (STAGES - 1);
        const uint32_t par = (i >> 2) & 1;
        wait_full(mb0 + 8 * slot, par);

        const float4* __restrict__ sbuf = reinterpret_cast<const float4*>(stage_buf[slot]);
        float4 v0 = sbuf[tid];
        float4 v1 = sbuf[tid + 256];
        const float s = v0.x + v0.z + v1.x + v1.z;
        if (i < 16) acc0 += s; else acc1 += s;

        __syncthreads();                         // all consumed before refill
        if (tid == 0 && i + STAGES < TOTAL_STAGES)
            issue_stage(mb0 + 8 * slot, sb0 + slot * STAGE_BYTES, base, i + STAGES);
    }

    // Block reduce both plane sums
    #pragma unroll
    for (int off = 16; off > 0; off >>= 1) {
        acc0 += __shfl_xor_sync(0xFFFFFFFFu, acc0, off);
        acc1 += __shfl_xor_sync(0xFFFFFFFFu, acc1, off);
    }
    if ((tid & 31) == 0) {
        warp_sums[0][tid >> 5] = acc0;
        warp_sums[1][tid >> 5] = acc1;
    }
    __syncthreads();

    if (tid == 0) {
        float s0 = warp_sums[0][0], s1 = warp_sums[1][0];
        #pragma unroll
        for (int w = 1; w < 8; ++w) { s0 += warp_sums[0][w]; s1 += warp_sums[1][w]; }
        g_pooled[2 * blk + 0] = s0 * (1.0f / 65536.0f);
        g_pooled[2 * blk + 1] = s1 * (1.0f / 65536.0f);
        __threadfence();

        unsigned int old = atomicAdd(&g_cnt_part[blk & 31].v, 1u);
        if (old == 15u) {                        // 512/32 = 16 per partition
            unsigned int old2 = atomicAdd(&g_cnt_final, 1u);
            if (old2 == 31u) {
                g_cnt_final = 0u;
                #pragma unroll
                for (int p = 0; p < 32; ++p) g_cnt_part[p].v = 0u;
                is_last = 1;
            }
        }
    }
    __syncthreads();
    if (!is_last) return;

    // ---------- Phase B: tiny MLP (globally-last block only) ----------
    #pragma unroll
    for (int k = 0; k < 4; ++k) {
        const int i = tid + k * 256;
        sp[i] = __ldcg(&g_pooled[i]);
    }
    __syncthreads();

    // hidden[b][j] = relu( sum_c pooled[b][c] * fc1_w[j][c] )
    {
        const int j  = tid & 31;
        const int bb = tid >> 5;
        const float4* __restrict__ w4 = reinterpret_cast<const float4*>(fc1_w) + j * 32;
        const float4* __restrict__ p4 = reinterpret_cast<const float4*>(sp) + bb * 32;
        float sacc = 0.0f;
        #pragma unroll
        for (int k = 0; k < 32; ++k) {
            float4 w = __ldg(&w4[k]);
            float4 p = p4[k];
            sacc = fmaf(w.x, p.x, sacc);
            sacc = fmaf(w.y, p.y, sacc);
            sacc = fmaf(w.z, p.z, sacc);
            sacc = fmaf(w.w, p.w, sacc);
        }
        sh[tid] = fmaxf(sacc, 0.0f);
    }
    __syncthreads();

    // out[b][c] = sum_j hidden[b][j] * fc2_w[c][j]
    #pragma unroll
    for (int k = 0; k < 4; ++k) {
        const int idx = tid + k * 256;           // b*128 + c
        const int bb  = idx >> 7;
        const int c   = idx & 127;
        const float4* __restrict__ w4 = reinterpret_cast<const float4*>(fc2_w) + c * 8;
        const float4* __restrict__ h4 = reinterpret_cast<const float4*>(sh) + bb * 8;
        float sacc = 0.0f;
        #pragma unroll
        for (int q = 0; q < 8; ++q) {
            float4 w = __ldg(&w4[q]);
            float4 h = h4[q];
            sacc = fmaf(w.x, h.x, sacc);
            sacc = fmaf(w.y, h.y, sacc);
            sacc = fmaf(w.z, h.z, sacc);
            sacc = fmaf(w.w, h.w, sacc);
        }
        out[idx] = sacc;
    }
}

extern "C" void kernel_launch(void* const* d_in, const int* in_sizes, int n_in,
                              void* d_out, int out_size) {
    // metadata order: a, b, attn_w, attn_b, fc1_w, fc2_w
    const float* bsrc  = (const float*)d_in[1];
    const float* fc1_w = (const float*)d_in[4];
    const float* fc2_w = (const float*)d_in[5];
    float* out = (float*)d_out;

    fused_kernel<<<512, 256>>>(bsrc, fc1_w, fc2_w, out);
}